// round 16
// baseline (speedup 1.0000x reference)
#include <cuda_runtime.h>
#include <cuda_fp16.h>
#include <math.h>
#include <stdint.h>

#define N_RAYS   32768
#define N_PLANES 32
#define NSAMP    (N_RAYS * N_PLANES)
#define EPSV     1e-8f
#define PERSIST_BLOCKS 148
#define THREADS  256

// ---------------- scratch ----------------
__device__ int   g_cnt;
__device__ int   g_sidx[NSAMP];
__device__ float g_world[NSAMP * 3];
__device__ float g_vd[NSAMP * 3];
__device__ float g_t[NSAMP];
__device__ float g_rgba[NSAMP * 4];

// ---------------- kernel 0 ----------------
__global__ void k_reset() { if (threadIdx.x == 0) g_cnt = 0; }

// ---------------- kernel 1: geometry + compaction ----------------
__global__ void __launch_bounds__(256) k_geom(
    const float* __restrict__ ndc, const float* __restrict__ cam_pos,
    const float* __restrict__ cam_R, const float* __restrict__ basis,
    const float* __restrict__ center, const float* __restrict__ wh)
{
    int gid = blockIdx.x * blockDim.x + threadIdx.x;
    if (gid >= NSAMP) return;
    int p = gid / N_RAYS;
    int n = gid - p * N_RAYS;

    float nd0 = ndc[n * 3 + 0], nd1 = ndc[n * 3 + 1], nd2 = ndc[n * 3 + 2];
    float d0 = cam_R[0] * nd0 + cam_R[1] * nd1 + cam_R[2] * nd2;
    float d1 = cam_R[3] * nd0 + cam_R[4] * nd1 + cam_R[5] * nd2;
    float d2 = cam_R[6] * nd0 + cam_R[7] * nd1 + cam_R[8] * nd2;
    float o0 = cam_pos[0], o1 = cam_pos[1], o2 = cam_pos[2];

    const float* B = basis + p * 9;
    float pn0 = B[2], pn1 = B[5], pn2 = B[8];
    float c0 = center[p * 3 + 0], c1 = center[p * 3 + 1], c2 = center[p * 3 + 2];

    float denom = pn0 * d0 + pn1 * d1 + pn2 * d2;
    if (fabsf(denom) < EPSV) denom = EPSV;
    float num = (c0 - o0) * pn0 + (c1 - o1) * pn1 + (c2 - o2) * pn2;
    float t = num / denom;

    float w0 = o0 + t * d0, w1 = o1 + t * d1, w2 = o2 + t * d2;
    float u = (w0 - c0) * B[0] + (w1 - c1) * B[3] + (w2 - c2) * B[6];
    float v = (w0 - c0) * B[1] + (w1 - c1) * B[4] + (w2 - c2) * B[7];
    bool inside = (fabsf(u) <= wh[p * 2 + 0] * 0.5f) && (fabsf(v) <= wh[p * 2 + 1] * 0.5f);
    bool hit = inside && (t > 0.0f);

    g_t[gid] = t;

    unsigned mask = __ballot_sync(0xffffffffu, hit);
    if (hit) {
        int lane   = threadIdx.x & 31;
        int leader = __ffs(mask) - 1;
        int rank   = __popc(mask & ((1u << lane) - 1u));
        int base   = 0;
        if (lane == leader) base = atomicAdd(&g_cnt, __popc(mask));
        base = __shfl_sync(mask, base, leader);
        int i = base + rank;
        g_sidx[i] = gid;
        g_world[i * 3 + 0] = w0;
        g_world[i * 3 + 1] = w1;
        g_world[i * 3 + 2] = w2;
        float vd0 = w0 - o0, vd1 = w1 - o1, vd2 = w2 - o2;
        float inv = 1.0f / (sqrtf(vd0 * vd0 + vd1 * vd1 + vd2 * vd2) + EPSV);
        g_vd[i * 3 + 0] = vd0 * inv;
        g_vd[i * 3 + 1] = vd1 * inv;
        g_vd[i * 3 + 2] = vd2 * inv;
    } else {
        float4 z = make_float4(0.f, 0.f, 0.f, 0.f);
        *reinterpret_cast<float4*>(&g_rgba[gid * 4]) = z;
    }
}

// ================= PTX mma/ldmatrix helpers =================
__device__ __forceinline__ uint32_t cvta_smem(const void* p) {
    uint32_t a;
    asm("{ .reg .u64 t; cvta.to.shared.u64 t, %1; cvt.u32.u64 %0, t; }" : "=r"(a) : "l"(p));
    return a;
}
__device__ __forceinline__ void ldm_x4(uint32_t r[4], uint32_t addr) {
    asm volatile("ldmatrix.sync.aligned.m8n8.x4.shared.b16 {%0,%1,%2,%3}, [%4];"
        : "=r"(r[0]), "=r"(r[1]), "=r"(r[2]), "=r"(r[3]) : "r"(addr));
}
__device__ __forceinline__ void ldm_x4t(uint32_t r[4], uint32_t addr) {
    asm volatile("ldmatrix.sync.aligned.m8n8.x4.trans.shared.b16 {%0,%1,%2,%3}, [%4];"
        : "=r"(r[0]), "=r"(r[1]), "=r"(r[2]), "=r"(r[3]) : "r"(addr));
}
__device__ __forceinline__ void mma_f16(float c[4], const uint32_t a[4], uint32_t b0, uint32_t b1) {
    asm volatile("mma.sync.aligned.m16n8k16.row.col.f32.f16.f16.f32 "
        "{%0,%1,%2,%3}, {%4,%5,%6,%7}, {%8,%9}, {%0,%1,%2,%3};"
        : "+f"(c[0]), "+f"(c[1]), "+f"(c[2]), "+f"(c[3])
        : "r"(a[0]), "r"(a[1]), "r"(a[2]), "r"(a[3]), "r"(b0), "r"(b1));
}
__device__ __forceinline__ uint32_t lane_mat_off(uint32_t lane, uint32_t ldB) {
    uint32_t i = lane & 7, m = lane >> 3;
    return (i + (m & 1) * 8) * ldB + (m >> 1) * 16;
}

// 64-row warp GEMM with B fragments preloaded in registers
template <int KSTEPS, int NB>
__device__ __forceinline__ void mma64_breg(
    uint32_t aBase, uint32_t ldaB, const uint32_t bf[KSTEPS][NB][4],
    float acc[4][2 * NB][4])
{
    #pragma unroll
    for (int ks = 0; ks < KSTEPS; ks++) {
        uint32_t a[4][4];
        #pragma unroll
        for (int mf = 0; mf < 4; mf++)
            ldm_x4(a[mf], aBase + mf * 16 * ldaB + ks * 32);
        #pragma unroll
        for (int p = 0; p < NB; p++) {
            #pragma unroll
            for (int mf = 0; mf < 4; mf++) {
                mma_f16(acc[mf][2 * p],     a[mf], bf[ks][p][0], bf[ks][p][1]);
                mma_f16(acc[mf][2 * p + 1], a[mf], bf[ks][p][2], bf[ks][p][3]);
            }
        }
    }
}

// 64-row warp GEMM with B from smem (used for Wc1)
template <int KSTEPS, int NB>
__device__ __forceinline__ void mma64(
    uint32_t aBase, uint32_t ldaB, uint32_t bBase, uint32_t ldbB,
    float acc[4][2 * NB][4])
{
    #pragma unroll
    for (int ks = 0; ks < KSTEPS; ks++) {
        uint32_t a[4][4];
        #pragma unroll
        for (int mf = 0; mf < 4; mf++)
            ldm_x4(a[mf], aBase + mf * 16 * ldaB + ks * 32);
        uint32_t bk = bBase + ks * 16 * ldbB;
        #pragma unroll
        for (int p = 0; p < NB; p++) {
            uint32_t b[4];
            ldm_x4t(b, bk + p * 32);
            #pragma unroll
            for (int mf = 0; mf < 4; mf++) {
                mma_f16(acc[mf][2 * p],     a[mf], b[0], b[1]);
                mma_f16(acc[mf][2 * p + 1], a[mf], b[2], b[3]);
            }
        }
    }
}

// ---------------- smem layout (bytes) ----------------
#define LDW_B   272
#define LDWC_B  144
#define LDA0_B  336
#define LDA1_B  272

#define SM_W0    0
#define SM_W1    (SM_W0 + 64 * LDW_B)
#define SM_WC1   (SM_W1 + 128 * LDW_B)
#define SM_A0    (SM_WC1 + 160 * LDWC_B)
#define A0_BLK   (64 * LDA0_B)
#define SM_A1    (SM_A0 + 2 * A0_BLK)
#define A1_BLK   (64 * LDA1_B)
#define SM_PART  (SM_A1 + 2 * A1_BLK)
#define SM_WC2T  (SM_PART + 8192)
#define SM_BC1   (SM_WC2T + 768)
#define SM_WAS   (SM_BC1 + 256)
#define SMEM_BYTES (SM_WAS + 512)           // 162816

#define HBAR(id) asm volatile("bar.sync %0, %1;" :: "r"(id), "r"(128) : "memory")

__device__ void stage_weight(const float* __restrict__ W, char* smem,
                             int off, int N, int Ksrc, int Kpad, int ldB, int tid)
{
    for (int idx = tid; idx < Kpad * N; idx += THREADS) {
        int k = idx / N;
        int n = idx - k * N;
        float w = (k < Ksrc) ? W[k * N + n] : 0.0f;
        *reinterpret_cast<__half*>(smem + off + k * ldB + n * 2) = __float2half_rn(w);
    }
}

__global__ void __launch_bounds__(THREADS, 1) k_mlp(
    const float* __restrict__ W0,  const float* __restrict__ b0,
    const float* __restrict__ W1,  const float* __restrict__ b1,
    const float* __restrict__ Wa,  const float* __restrict__ ba,
    const float* __restrict__ Wc1, const float* __restrict__ bc1,
    const float* __restrict__ Wc2, const float* __restrict__ bc2)
{
    extern __shared__ char smem[];
    const uint32_t smem_u = cvta_smem(smem);

    const int tid  = threadIdx.x;
    const int half = tid >> 7;
    const int ht   = tid & 127;
    const int lane = tid & 31;
    const int hw   = ht >> 5;
    const int cb32 = hw * 32;
    const int cb16 = hw * 16;
    const int r    = ht >> 1;
    const int q    = ht & 1;
    const int barid = half + 1;

    const int a0b = SM_A0 + half * A0_BLK;
    const int a1b = SM_A1 + half * A1_BLK;
    float* part = reinterpret_cast<float*>(smem + SM_PART + half * 4096);
    float* Wc2t = reinterpret_cast<float*>(smem + SM_WC2T);
    float* bc1s = reinterpret_cast<float*>(smem + SM_BC1);
    float* Was  = reinterpret_cast<float*>(smem + SM_WAS);

    const float ba0  = ba[0];
    const float bc20 = bc2[0], bc21 = bc2[1], bc22 = bc2[2];
    const __half hz = __float2half_rn(0.f);

    const uint32_t lo336 = lane_mat_off(lane, LDA0_B);
    const uint32_t lo272 = lane_mat_off(lane, LDW_B);
    const uint32_t lo144 = lane_mat_off(lane, LDWC_B);

    const uint32_t A0u = smem_u + a0b + lo336;
    const uint32_t A1u = smem_u + a1b + lo272;
    const uint32_t W0u = smem_u + SM_W0 + cb32 * 2 + lo272;
    const uint32_t W1u = smem_u + SM_W1 + cb32 * 2 + lo272;
    const uint32_t Wcu = smem_u + SM_WC1 + cb16 * 2 + lo144;

    const int ecol = (lane & 3) * 2;
    const int erow = lane >> 2;

    // ---- one-time staging ----
    stage_weight(W0,  smem, SM_W0,  128, 60,  64,  LDW_B,  tid);
    stage_weight(W1,  smem, SM_W1,  128, 128, 128, LDW_B,  tid);
    stage_weight(Wc1, smem, SM_WC1, 64,  152, 160, LDWC_B, tid);
    if (tid < 192) Wc2t[(tid % 3) * 64 + tid / 3] = Wc2[tid];
    if (tid >= 192 && tid < 256) bc1s[tid - 192] = bc1[tid - 192];
    if (tid < 128) Was[tid] = Wa[tid];
    for (int idx = tid; idx < 2 * 64 * 8; idx += THREADS) {
        int hh = idx >> 9, rr = (idx >> 3) & 63, cc = 152 + (idx & 7);
        *reinterpret_cast<__half*>(smem + SM_A0 + hh * A0_BLK + rr * LDA0_B + cc * 2) = hz;
    }
    __syncthreads();

    // ---- hoist W0/W1 B-fragments into registers (constant across tiles) ----
    uint32_t w0f[4][2][4];
    #pragma unroll
    for (int ks = 0; ks < 4; ks++)
        #pragma unroll
        for (int p = 0; p < 2; p++)
            ldm_x4t(w0f[ks][p], W0u + ks * 16 * LDW_B + p * 32);
    uint32_t w1f[8][2][4];
    #pragma unroll
    for (int ks = 0; ks < 8; ks++)
        #pragma unroll
        for (int p = 0; p < 2; p++)
            ldm_x4t(w1f[ks][p], W1u + ks * 16 * LDW_B + p * 32);

    const int cnt    = g_cnt;
    const int nTiles = (cnt + 63) >> 6;

    for (int tile = blockIdx.x * 2 + half; tile < nTiles; tile += gridDim.x * 2) {
        const int gi   = (tile << 6) + r;
        const bool live = gi < cnt;

        // ===== S1: pos encode + dir encode (2 threads/sample) =====
        {
            char* rw = smem + a0b + r * LDA0_B;
            float xa = 0.f, xb = 0.f, va = 0.f, vb = 0.f;
            if (live) {
                const float* wp = &g_world[gi * 3];
                const float* vp = &g_vd[gi * 3];
                if (q == 0) { xa = wp[0]; xb = wp[2];         va = vp[0]; vb = vp[2]; }
                else        { xa = wp[1]; xb = wp[2] * 32.f;  va = vp[1]; vb = vp[2] * 4.f; }
            }
            float s, c;
            if (live) sincosf(xa, &s, &c); else { s = 0.f; c = 0.f; }
            {
                int base = q ? 20 : 0;
                #pragma unroll
                for (int j = 0; j < 10; j++) {
                    *reinterpret_cast<__half*>(rw + (base + j) * 2)      = __float2half_rn(s);
                    *reinterpret_cast<__half*>(rw + (base + 10 + j) * 2) = __float2half_rn(c);
                    float ns = 2.f * s * c;
                    float nc = fmaf(-2.f * s, s, 1.f);
                    s = ns; c = nc;
                }
            }
            if (live) sincosf(xb, &s, &c); else { s = 0.f; c = 0.f; }
            {
                int base = q ? 45 : 40;
                #pragma unroll
                for (int j = 0; j < 5; j++) {
                    *reinterpret_cast<__half*>(rw + (base + j) * 2)      = __float2half_rn(s);
                    *reinterpret_cast<__half*>(rw + (base + 10 + j) * 2) = __float2half_rn(c);
                    float ns = 2.f * s * c;
                    float nc = fmaf(-2.f * s, s, 1.f);
                    s = ns; c = nc;
                }
            }
            if (live) sincosf(va, &s, &c); else { s = 0.f; c = 0.f; }
            {
                int base = q ? 136 : 128;
                #pragma unroll
                for (int j = 0; j < 4; j++) {
                    *reinterpret_cast<__half*>(rw + (base + j) * 2)     = __float2half_rn(s);
                    *reinterpret_cast<__half*>(rw + (base + 4 + j) * 2) = __float2half_rn(c);
                    float ns = 2.f * s * c;
                    float nc = fmaf(-2.f * s, s, 1.f);
                    s = ns; c = nc;
                }
            }
            if (live) sincosf(vb, &s, &c); else { s = 0.f; c = 0.f; }
            {
                int base = q ? 146 : 144;
                #pragma unroll
                for (int j = 0; j < 2; j++) {
                    *reinterpret_cast<__half*>(rw + (base + j) * 2)     = __float2half_rn(s);
                    *reinterpret_cast<__half*>(rw + (base + 4 + j) * 2) = __float2half_rn(c);
                    float ns = 2.f * s * c;
                    float nc = fmaf(-2.f * s, s, 1.f);
                    s = ns; c = nc;
                }
            }
            if (q == 1) {
                #pragma unroll
                for (int cc = 60; cc < 64; cc++)
                    *reinterpret_cast<__half*>(rw + cc * 2) = hz;
            }
        }
        HBAR(barid);

        // ===== L0: h0 = relu(enc @ W0 + b0) -> A1 =====
        {
            float acc[4][4][4];
            #pragma unroll
            for (int mf = 0; mf < 4; mf++)
                #pragma unroll
                for (int i = 0; i < 4; i++)
                    #pragma unroll
                    for (int j = 0; j < 4; j++) acc[mf][i][j] = 0.f;
            mma64_breg<4, 2>(A0u, LDA0_B, w0f, acc);
            #pragma unroll
            for (int mf = 0; mf < 4; mf++) {
                int rlo = mf * 16 + erow, rhi = rlo + 8;
                char* dlo = smem + a1b + rlo * LDA1_B;
                char* dhi = smem + a1b + rhi * LDA1_B;
                #pragma unroll
                for (int nf = 0; nf < 4; nf++) {
                    int col = cb32 + nf * 8 + ecol;
                    float2 bv = __ldg(reinterpret_cast<const float2*>(b0 + col));
                    float v0 = fmaxf(acc[mf][nf][0] + bv.x, 0.f);
                    float v1 = fmaxf(acc[mf][nf][1] + bv.y, 0.f);
                    float v2 = fmaxf(acc[mf][nf][2] + bv.x, 0.f);
                    float v3 = fmaxf(acc[mf][nf][3] + bv.y, 0.f);
                    __half2 h01 = __floats2half2_rn(v0, v1);
                    __half2 h23 = __floats2half2_rn(v2, v3);
                    *reinterpret_cast<uint32_t*>(dlo + col * 2) = *reinterpret_cast<uint32_t*>(&h01);
                    *reinterpret_cast<uint32_t*>(dhi + col * 2) = *reinterpret_cast<uint32_t*>(&h23);
                }
            }
        }
        HBAR(barid);

        // ===== L1: h1 = relu(h0 @ W1 + b1) -> A0 cols 0..127; alpha partials =====
        {
            float acc[4][4][4];
            #pragma unroll
            for (int mf = 0; mf < 4; mf++)
                #pragma unroll
                for (int i = 0; i < 4; i++)
                    #pragma unroll
                    for (int j = 0; j < 4; j++) acc[mf][i][j] = 0.f;
            mma64_breg<8, 2>(A1u, LDA1_B, w1f, acc);
            #pragma unroll
            for (int mf = 0; mf < 4; mf++) {
                int rlo = mf * 16 + erow, rhi = rlo + 8;
                char* dlo = smem + a0b + rlo * LDA0_B;
                char* dhi = smem + a0b + rhi * LDA0_B;
                float alo = 0.f, ahi = 0.f;
                #pragma unroll
                for (int nf = 0; nf < 4; nf++) {
                    int col = cb32 + nf * 8 + ecol;
                    float2 bv = __ldg(reinterpret_cast<const float2*>(b1 + col));
                    float2 wv = *reinterpret_cast<const float2*>(Was + col);
                    float v0 = fmaxf(acc[mf][nf][0] + bv.x, 0.f);
                    float v1 = fmaxf(acc[mf][nf][1] + bv.y, 0.f);
                    float v2 = fmaxf(acc[mf][nf][2] + bv.x, 0.f);
                    float v3 = fmaxf(acc[mf][nf][3] + bv.y, 0.f);
                    alo = fmaf(v0, wv.x, alo); alo = fmaf(v1, wv.y, alo);
                    ahi = fmaf(v2, wv.x, ahi); ahi = fmaf(v3, wv.y, ahi);
                    __half2 h01 = __floats2half2_rn(v0, v1);
                    __half2 h23 = __floats2half2_rn(v2, v3);
                    *reinterpret_cast<uint32_t*>(dlo + col * 2) = *reinterpret_cast<uint32_t*>(&h01);
                    *reinterpret_cast<uint32_t*>(dhi + col * 2) = *reinterpret_cast<uint32_t*>(&h23);
                }
                alo += __shfl_xor_sync(0xffffffffu, alo, 1);
                alo += __shfl_xor_sync(0xffffffffu, alo, 2);
                ahi += __shfl_xor_sync(0xffffffffu, ahi, 1);
                ahi += __shfl_xor_sync(0xffffffffu, ahi, 2);
                if ((lane & 3) == 0) {
                    part[rlo * 16 + hw * 4 + 3] = alo;
                    part[rhi * 16 + hw * 4 + 3] = ahi;
                }
            }
        }
        HBAR(barid);

        // ===== Wc1: hc = relu([h1|denc] @ Wc1 + bc1); rgb partials =====
        {
            float acc[4][2][4];
            #pragma unroll
            for (int mf = 0; mf < 4; mf++)
                #pragma unroll
                for (int i = 0; i < 2; i++)
                    #pragma unroll
                    for (int j = 0; j < 4; j++) acc[mf][i][j] = 0.f;
            mma64<10, 1>(A0u, LDA0_B, Wcu, LDWC_B, acc);
            #pragma unroll
            for (int mf = 0; mf < 4; mf++) {
                int rlo = mf * 16 + erow, rhi = rlo + 8;
                float plo[3] = {0.f, 0.f, 0.f}, phi[3] = {0.f, 0.f, 0.f};
                #pragma unroll
                for (int nf = 0; nf < 2; nf++) {
                    int col = cb16 + nf * 8 + ecol;
                    float2 bcv = *reinterpret_cast<const float2*>(bc1s + col);
                    float v0 = fmaxf(acc[mf][nf][0] + bcv.x, 0.f);
                    float v1 = fmaxf(acc[mf][nf][1] + bcv.y, 0.f);
                    float v2 = fmaxf(acc[mf][nf][2] + bcv.x, 0.f);
                    float v3 = fmaxf(acc[mf][nf][3] + bcv.y, 0.f);
                    #pragma unroll
                    for (int j = 0; j < 3; j++) {
                        float2 w = *reinterpret_cast<const float2*>(Wc2t + j * 64 + col);
                        plo[j] = fmaf(v0, w.x, plo[j]); plo[j] = fmaf(v1, w.y, plo[j]);
                        phi[j] = fmaf(v2, w.x, phi[j]); phi[j] = fmaf(v3, w.y, phi[j]);
                    }
                }
                #pragma unroll
                for (int j = 0; j < 3; j++) {
                    plo[j] += __shfl_xor_sync(0xffffffffu, plo[j], 1);
                    plo[j] += __shfl_xor_sync(0xffffffffu, plo[j], 2);
                    phi[j] += __shfl_xor_sync(0xffffffffu, phi[j], 1);
                    phi[j] += __shfl_xor_sync(0xffffffffu, phi[j], 2);
                }
                if ((lane & 3) == 0) {
                    #pragma unroll
                    for (int j = 0; j < 3; j++) {
                        part[rlo * 16 + hw * 4 + j] = plo[j];
                        part[rhi * 16 + hw * 4 + j] = phi[j];
                    }
                }
            }
        }
        HBAR(barid);

        // ===== combine + scatter (64 threads per half) =====
        if (ht < 64) {
            int gi2 = (tile << 6) + ht;
            if (gi2 < cnt) {
                const float* pp = part + ht * 16;
                float r0 = bc20 + pp[0] + pp[4] + pp[8]  + pp[12];
                float r1 = bc21 + pp[1] + pp[5] + pp[9]  + pp[13];
                float r2 = bc22 + pp[2] + pp[6] + pp[10] + pp[14];
                float aa = ba0  + pp[3] + pp[7] + pp[11] + pp[15];
                float4 outv;
                outv.x = 1.0f / (1.0f + __expf(-r0));
                outv.y = 1.0f / (1.0f + __expf(-r1));
                outv.z = 1.0f / (1.0f + __expf(-r2));
                outv.w = 1.0f / (1.0f + __expf(-aa));
                *reinterpret_cast<float4*>(&g_rgba[g_sidx[gi2] * 4]) = outv;
            }
        }
        HBAR(barid);
    }
}

// ---------------- kernel 5: composite, 2 threads/ray (associative merge) ----------------
__global__ void __launch_bounds__(128) k_composite(float* __restrict__ out)
{
    int idx = blockIdx.x * blockDim.x + threadIdx.x;
    int n = idx >> 1;          // ray
    int q = idx & 1;           // segment: 0 = near 16, 1 = far 16
    if (n >= N_RAYS) return;

    float tv[N_PLANES];
    int   pv[N_PLANES];
    #pragma unroll
    for (int p = 0; p < N_PLANES; p++) {
        tv[p] = g_t[p * N_RAYS + n];
        pv[p] = p;
    }

    #pragma unroll
    for (int k = 2; k <= N_PLANES; k <<= 1) {
        #pragma unroll
        for (int j = k >> 1; j > 0; j >>= 1) {
            #pragma unroll
            for (int i = 0; i < N_PLANES; i++) {
                int l = i ^ j;
                if (l > i) {
                    bool up = ((i & k) == 0);
                    bool sw = up ? (tv[i] > tv[l]) : (tv[i] < tv[l]);
                    if (sw) {
                        float tt = tv[i]; tv[i] = tv[l]; tv[l] = tt;
                        int   pp = pv[i]; pv[i] = pv[l]; pv[l] = pp;
                    }
                }
            }
        }
    }

    // composite own 16 sorted ranks
    float trans = 1.0f, sw = 0.0f, depth = 0.0f;
    float c0 = 0.f, c1 = 0.f, c2 = 0.f;
    int s0 = q * 16;
    #pragma unroll
    for (int s = 0; s < 16; s++) {
        int p = pv[s0 + s];
        float4 rg = *reinterpret_cast<const float4*>(&g_rgba[(p * N_RAYS + n) * 4]);
        float a = rg.w;
        float w = a * trans;
        depth = fmaf(tv[s0 + s], w, depth);
        c0 = fmaf(rg.x, w, c0);
        c1 = fmaf(rg.y, w, c1);
        c2 = fmaf(rg.z, w, c2);
        sw += w;
        trans *= (1.0f - a);
    }

    // merge: total = near + trans_near * far
    float p_c0 = __shfl_xor_sync(0xffffffffu, c0, 1);
    float p_c1 = __shfl_xor_sync(0xffffffffu, c1, 1);
    float p_c2 = __shfl_xor_sync(0xffffffffu, c2, 1);
    float p_dp = __shfl_xor_sync(0xffffffffu, depth, 1);
    float p_sw = __shfl_xor_sync(0xffffffffu, sw, 1);
    if (q == 0) {
        c0 = fmaf(trans, p_c0, c0);
        c1 = fmaf(trans, p_c1, c1);
        c2 = fmaf(trans, p_c2, c2);
        depth = fmaf(trans, p_dp, depth);
        sw = fmaf(trans, p_sw, sw);
        float bg = 1.0f - sw;
        float4 o;
        o.x = c0 + bg;
        o.y = c1 + bg;
        o.z = c2 + bg;
        o.w = depth;
        *reinterpret_cast<float4*>(&out[n * 4]) = o;
    }
}

// ---------------- launch ----------------
extern "C" void kernel_launch(void* const* d_in, const int* in_sizes, int n_in,
                              void* d_out, int out_size)
{
    const float* ndc    = (const float*)d_in[0];
    const float* campos = (const float*)d_in[1];
    const float* camR   = (const float*)d_in[2];
    const float* basis  = (const float*)d_in[3];
    const float* center = (const float*)d_in[4];
    const float* wh     = (const float*)d_in[5];
    const float* W0     = (const float*)d_in[6];
    const float* b0     = (const float*)d_in[7];
    const float* W1     = (const float*)d_in[8];
    const float* b1     = (const float*)d_in[9];
    const float* Wa     = (const float*)d_in[10];
    const float* ba     = (const float*)d_in[11];
    const float* Wc1    = (const float*)d_in[12];
    const float* bc1    = (const float*)d_in[13];
    const float* Wc2    = (const float*)d_in[14];
    const float* bc2    = (const float*)d_in[15];
    float* out = (float*)d_out;

    static int smem_set = 0;
    if (!smem_set) {
        cudaFuncSetAttribute(k_mlp, cudaFuncAttributeMaxDynamicSharedMemorySize, SMEM_BYTES);
        smem_set = 1;
    }

    k_reset<<<1, 32>>>();
    k_geom<<<NSAMP / 256, 256>>>(ndc, campos, camR, basis, center, wh);
    k_mlp<<<PERSIST_BLOCKS, THREADS, SMEM_BYTES>>>(W0, b0, W1, b1, Wa, ba, Wc1, bc1, Wc2, bc2);
    k_composite<<<(N_RAYS * 2 + 127) / 128, 128>>>(out);
}

// round 17
// speedup vs baseline: 1.1794x; 1.1794x over previous
#include <cuda_runtime.h>
#include <cuda_fp16.h>
#include <math.h>
#include <stdint.h>

#define N_RAYS   32768
#define N_PLANES 32
#define NSAMP    (N_RAYS * N_PLANES)
#define EPSV     1e-8f
#define PERSIST_BLOCKS 148
#define THREADS  256

// ---------------- scratch ----------------
__device__ int   g_cnt;
__device__ int   g_sidx[NSAMP];
__device__ float g_world[NSAMP * 3];
__device__ float g_vd[NSAMP * 3];
__device__ float g_t[NSAMP];
__device__ float g_rgba[NSAMP * 4];

// ---------------- kernel 0 ----------------
__global__ void k_reset() { if (threadIdx.x == 0) g_cnt = 0; }

// ---------------- kernel 1: geometry + compaction ----------------
__global__ void __launch_bounds__(256) k_geom(
    const float* __restrict__ ndc, const float* __restrict__ cam_pos,
    const float* __restrict__ cam_R, const float* __restrict__ basis,
    const float* __restrict__ center, const float* __restrict__ wh)
{
    int gid = blockIdx.x * blockDim.x + threadIdx.x;
    if (gid >= NSAMP) return;
    int p = gid / N_RAYS;
    int n = gid - p * N_RAYS;

    float nd0 = ndc[n * 3 + 0], nd1 = ndc[n * 3 + 1], nd2 = ndc[n * 3 + 2];
    float d0 = cam_R[0] * nd0 + cam_R[1] * nd1 + cam_R[2] * nd2;
    float d1 = cam_R[3] * nd0 + cam_R[4] * nd1 + cam_R[5] * nd2;
    float d2 = cam_R[6] * nd0 + cam_R[7] * nd1 + cam_R[8] * nd2;
    float o0 = cam_pos[0], o1 = cam_pos[1], o2 = cam_pos[2];

    const float* B = basis + p * 9;
    float pn0 = B[2], pn1 = B[5], pn2 = B[8];
    float c0 = center[p * 3 + 0], c1 = center[p * 3 + 1], c2 = center[p * 3 + 2];

    float denom = pn0 * d0 + pn1 * d1 + pn2 * d2;
    if (fabsf(denom) < EPSV) denom = EPSV;
    float num = (c0 - o0) * pn0 + (c1 - o1) * pn1 + (c2 - o2) * pn2;
    float t = num / denom;

    float w0 = o0 + t * d0, w1 = o1 + t * d1, w2 = o2 + t * d2;
    float u = (w0 - c0) * B[0] + (w1 - c1) * B[3] + (w2 - c2) * B[6];
    float v = (w0 - c0) * B[1] + (w1 - c1) * B[4] + (w2 - c2) * B[7];
    bool inside = (fabsf(u) <= wh[p * 2 + 0] * 0.5f) && (fabsf(v) <= wh[p * 2 + 1] * 0.5f);
    bool hit = inside && (t > 0.0f);

    g_t[gid] = t;

    unsigned mask = __ballot_sync(0xffffffffu, hit);
    if (hit) {
        int lane   = threadIdx.x & 31;
        int leader = __ffs(mask) - 1;
        int rank   = __popc(mask & ((1u << lane) - 1u));
        int base   = 0;
        if (lane == leader) base = atomicAdd(&g_cnt, __popc(mask));
        base = __shfl_sync(mask, base, leader);
        int i = base + rank;
        g_sidx[i] = gid;
        g_world[i * 3 + 0] = w0;
        g_world[i * 3 + 1] = w1;
        g_world[i * 3 + 2] = w2;
        float vd0 = w0 - o0, vd1 = w1 - o1, vd2 = w2 - o2;
        float inv = 1.0f / (sqrtf(vd0 * vd0 + vd1 * vd1 + vd2 * vd2) + EPSV);
        g_vd[i * 3 + 0] = vd0 * inv;
        g_vd[i * 3 + 1] = vd1 * inv;
        g_vd[i * 3 + 2] = vd2 * inv;
    } else {
        float4 z = make_float4(0.f, 0.f, 0.f, 0.f);
        *reinterpret_cast<float4*>(&g_rgba[gid * 4]) = z;
    }
}

// ================= PTX mma/ldmatrix helpers =================
__device__ __forceinline__ uint32_t cvta_smem(const void* p) {
    uint32_t a;
    asm("{ .reg .u64 t; cvta.to.shared.u64 t, %1; cvt.u32.u64 %0, t; }" : "=r"(a) : "l"(p));
    return a;
}
__device__ __forceinline__ void ldm_x4(uint32_t r[4], uint32_t addr) {
    asm volatile("ldmatrix.sync.aligned.m8n8.x4.shared.b16 {%0,%1,%2,%3}, [%4];"
        : "=r"(r[0]), "=r"(r[1]), "=r"(r[2]), "=r"(r[3]) : "r"(addr));
}
__device__ __forceinline__ void ldm_x4t(uint32_t r[4], uint32_t addr) {
    asm volatile("ldmatrix.sync.aligned.m8n8.x4.trans.shared.b16 {%0,%1,%2,%3}, [%4];"
        : "=r"(r[0]), "=r"(r[1]), "=r"(r[2]), "=r"(r[3]) : "r"(addr));
}
__device__ __forceinline__ void mma_f16(float c[4], const uint32_t a[4], uint32_t b0, uint32_t b1) {
    asm volatile("mma.sync.aligned.m16n8k16.row.col.f32.f16.f16.f32 "
        "{%0,%1,%2,%3}, {%4,%5,%6,%7}, {%8,%9}, {%0,%1,%2,%3};"
        : "+f"(c[0]), "+f"(c[1]), "+f"(c[2]), "+f"(c[3])
        : "r"(a[0]), "r"(a[1]), "r"(a[2]), "r"(a[3]), "r"(b0), "r"(b1));
}
__device__ __forceinline__ uint32_t lane_mat_off(uint32_t lane, uint32_t ldB) {
    uint32_t i = lane & 7, m = lane >> 3;
    return (i + (m & 1) * 8) * ldB + (m >> 1) * 16;
}

// 64-row warp GEMM: B fragments reused across all 4 m-frags (B from smem)
template <int KSTEPS, int NB>
__device__ __forceinline__ void mma64(
    uint32_t aBase, uint32_t ldaB, uint32_t bBase, uint32_t ldbB,
    float acc[4][2 * NB][4])
{
    #pragma unroll
    for (int ks = 0; ks < KSTEPS; ks++) {
        uint32_t a[4][4];
        #pragma unroll
        for (int mf = 0; mf < 4; mf++)
            ldm_x4(a[mf], aBase + mf * 16 * ldaB + ks * 32);
        uint32_t bk = bBase + ks * 16 * ldbB;
        #pragma unroll
        for (int p = 0; p < NB; p++) {
            uint32_t b[4];
            ldm_x4t(b, bk + p * 32);
            #pragma unroll
            for (int mf = 0; mf < 4; mf++) {
                mma_f16(acc[mf][2 * p],     a[mf], b[0], b[1]);
                mma_f16(acc[mf][2 * p + 1], a[mf], b[2], b[3]);
            }
        }
    }
}

// ---------------- smem layout (bytes) ----------------
#define LDW_B   272
#define LDWC_B  144
#define LDA0_B  336
#define LDA1_B  272

#define SM_W0    0
#define SM_W1    (SM_W0 + 64 * LDW_B)
#define SM_WC1   (SM_W1 + 128 * LDW_B)
#define SM_A0    (SM_WC1 + 160 * LDWC_B)
#define A0_BLK   (64 * LDA0_B)
#define SM_A1    (SM_A0 + 2 * A0_BLK)
#define A1_BLK   (64 * LDA1_B)
#define SM_PART  (SM_A1 + 2 * A1_BLK)
#define SM_WC2T  (SM_PART + 8192)
#define SM_BC1   (SM_WC2T + 768)
#define SM_WAS   (SM_BC1 + 256)
#define SMEM_BYTES (SM_WAS + 512)           // 162816

#define HBAR(id) asm volatile("bar.sync %0, %1;" :: "r"(id), "r"(128) : "memory")

__device__ void stage_weight(const float* __restrict__ W, char* smem,
                             int off, int N, int Ksrc, int Kpad, int ldB, int tid)
{
    for (int idx = tid; idx < Kpad * N; idx += THREADS) {
        int k = idx / N;
        int n = idx - k * N;
        float w = (k < Ksrc) ? W[k * N + n] : 0.0f;
        *reinterpret_cast<__half*>(smem + off + k * ldB + n * 2) = __float2half_rn(w);
    }
}

__global__ void __launch_bounds__(THREADS, 1) k_mlp(
    const float* __restrict__ W0,  const float* __restrict__ b0,
    const float* __restrict__ W1,  const float* __restrict__ b1,
    const float* __restrict__ Wa,  const float* __restrict__ ba,
    const float* __restrict__ Wc1, const float* __restrict__ bc1,
    const float* __restrict__ Wc2, const float* __restrict__ bc2)
{
    extern __shared__ char smem[];
    const uint32_t smem_u = cvta_smem(smem);

    const int tid  = threadIdx.x;
    const int half = tid >> 7;
    const int ht   = tid & 127;
    const int lane = tid & 31;
    const int hw   = ht >> 5;
    const int cb32 = hw * 32;
    const int cb16 = hw * 16;
    const int r    = ht >> 1;
    const int q    = ht & 1;
    const int barid = half + 1;

    const int a0b = SM_A0 + half * A0_BLK;
    const int a1b = SM_A1 + half * A1_BLK;
    float* part = reinterpret_cast<float*>(smem + SM_PART + half * 4096);
    float* Wc2t = reinterpret_cast<float*>(smem + SM_WC2T);
    float* bc1s = reinterpret_cast<float*>(smem + SM_BC1);
    float* Was  = reinterpret_cast<float*>(smem + SM_WAS);

    const float ba0  = ba[0];
    const float bc20 = bc2[0], bc21 = bc2[1], bc22 = bc2[2];
    const __half hz = __float2half_rn(0.f);

    const uint32_t lo336 = lane_mat_off(lane, LDA0_B);
    const uint32_t lo272 = lane_mat_off(lane, LDW_B);
    const uint32_t lo144 = lane_mat_off(lane, LDWC_B);

    const uint32_t A0u = smem_u + a0b + lo336;
    const uint32_t A1u = smem_u + a1b + lo272;
    const uint32_t W0u = smem_u + SM_W0 + cb32 * 2 + lo272;
    const uint32_t W1u = smem_u + SM_W1 + cb32 * 2 + lo272;
    const uint32_t Wcu = smem_u + SM_WC1 + cb16 * 2 + lo144;

    const int ecol = (lane & 3) * 2;
    const int erow = lane >> 2;

    // ---- one-time staging ----
    stage_weight(W0,  smem, SM_W0,  128, 60,  64,  LDW_B,  tid);
    stage_weight(W1,  smem, SM_W1,  128, 128, 128, LDW_B,  tid);
    stage_weight(Wc1, smem, SM_WC1, 64,  152, 160, LDWC_B, tid);
    if (tid < 192) Wc2t[(tid % 3) * 64 + tid / 3] = Wc2[tid];
    if (tid >= 192 && tid < 256) bc1s[tid - 192] = bc1[tid - 192];
    if (tid < 128) Was[tid] = Wa[tid];
    for (int idx = tid; idx < 2 * 64 * 8; idx += THREADS) {
        int hh = idx >> 9, rr = (idx >> 3) & 63, cc = 152 + (idx & 7);
        *reinterpret_cast<__half*>(smem + SM_A0 + hh * A0_BLK + rr * LDA0_B + cc * 2) = hz;
    }
    __syncthreads();

    const int cnt    = g_cnt;
    const int nTiles = (cnt + 63) >> 6;

    for (int tile = blockIdx.x * 2 + half; tile < nTiles; tile += gridDim.x * 2) {
        const int gi   = (tile << 6) + r;
        const bool live = gi < cnt;

        // ===== S1: pos encode + dir encode (2 threads/sample) =====
        {
            char* rw = smem + a0b + r * LDA0_B;
            float xa = 0.f, xb = 0.f, va = 0.f, vb = 0.f;
            if (live) {
                const float* wp = &g_world[gi * 3];
                const float* vp = &g_vd[gi * 3];
                if (q == 0) { xa = wp[0]; xb = wp[2];         va = vp[0]; vb = vp[2]; }
                else        { xa = wp[1]; xb = wp[2] * 32.f;  va = vp[1]; vb = vp[2] * 4.f; }
            }
            float s, c;
            if (live) sincosf(xa, &s, &c); else { s = 0.f; c = 0.f; }
            {
                int base = q ? 20 : 0;
                #pragma unroll
                for (int j = 0; j < 10; j++) {
                    *reinterpret_cast<__half*>(rw + (base + j) * 2)      = __float2half_rn(s);
                    *reinterpret_cast<__half*>(rw + (base + 10 + j) * 2) = __float2half_rn(c);
                    float ns = 2.f * s * c;
                    float nc = fmaf(-2.f * s, s, 1.f);
                    s = ns; c = nc;
                }
            }
            if (live) sincosf(xb, &s, &c); else { s = 0.f; c = 0.f; }
            {
                int base = q ? 45 : 40;
                #pragma unroll
                for (int j = 0; j < 5; j++) {
                    *reinterpret_cast<__half*>(rw + (base + j) * 2)      = __float2half_rn(s);
                    *reinterpret_cast<__half*>(rw + (base + 10 + j) * 2) = __float2half_rn(c);
                    float ns = 2.f * s * c;
                    float nc = fmaf(-2.f * s, s, 1.f);
                    s = ns; c = nc;
                }
            }
            if (live) sincosf(va, &s, &c); else { s = 0.f; c = 0.f; }
            {
                int base = q ? 136 : 128;
                #pragma unroll
                for (int j = 0; j < 4; j++) {
                    *reinterpret_cast<__half*>(rw + (base + j) * 2)     = __float2half_rn(s);
                    *reinterpret_cast<__half*>(rw + (base + 4 + j) * 2) = __float2half_rn(c);
                    float ns = 2.f * s * c;
                    float nc = fmaf(-2.f * s, s, 1.f);
                    s = ns; c = nc;
                }
            }
            if (live) sincosf(vb, &s, &c); else { s = 0.f; c = 0.f; }
            {
                int base = q ? 146 : 144;
                #pragma unroll
                for (int j = 0; j < 2; j++) {
                    *reinterpret_cast<__half*>(rw + (base + j) * 2)     = __float2half_rn(s);
                    *reinterpret_cast<__half*>(rw + (base + 4 + j) * 2) = __float2half_rn(c);
                    float ns = 2.f * s * c;
                    float nc = fmaf(-2.f * s, s, 1.f);
                    s = ns; c = nc;
                }
            }
            if (q == 1) {
                #pragma unroll
                for (int cc = 60; cc < 64; cc++)
                    *reinterpret_cast<__half*>(rw + cc * 2) = hz;
            }
        }
        HBAR(barid);

        // ===== L0: h0 = relu(enc @ W0 + b0) -> A1 =====
        {
            float acc[4][4][4];
            #pragma unroll
            for (int mf = 0; mf < 4; mf++)
                #pragma unroll
                for (int i = 0; i < 4; i++)
                    #pragma unroll
                    for (int j = 0; j < 4; j++) acc[mf][i][j] = 0.f;
            mma64<4, 2>(A0u, LDA0_B, W0u, LDW_B, acc);
            #pragma unroll
            for (int mf = 0; mf < 4; mf++) {
                int rlo = mf * 16 + erow, rhi = rlo + 8;
                char* dlo = smem + a1b + rlo * LDA1_B;
                char* dhi = smem + a1b + rhi * LDA1_B;
                #pragma unroll
                for (int nf = 0; nf < 4; nf++) {
                    int col = cb32 + nf * 8 + ecol;
                    float2 bv = __ldg(reinterpret_cast<const float2*>(b0 + col));
                    float v0 = fmaxf(acc[mf][nf][0] + bv.x, 0.f);
                    float v1 = fmaxf(acc[mf][nf][1] + bv.y, 0.f);
                    float v2 = fmaxf(acc[mf][nf][2] + bv.x, 0.f);
                    float v3 = fmaxf(acc[mf][nf][3] + bv.y, 0.f);
                    __half2 h01 = __floats2half2_rn(v0, v1);
                    __half2 h23 = __floats2half2_rn(v2, v3);
                    *reinterpret_cast<uint32_t*>(dlo + col * 2) = *reinterpret_cast<uint32_t*>(&h01);
                    *reinterpret_cast<uint32_t*>(dhi + col * 2) = *reinterpret_cast<uint32_t*>(&h23);
                }
            }
        }
        HBAR(barid);

        // ===== L1: h1 = relu(h0 @ W1 + b1) -> A0 cols 0..127; alpha partials =====
        {
            float acc[4][4][4];
            #pragma unroll
            for (int mf = 0; mf < 4; mf++)
                #pragma unroll
                for (int i = 0; i < 4; i++)
                    #pragma unroll
                    for (int j = 0; j < 4; j++) acc[mf][i][j] = 0.f;
            mma64<8, 2>(A1u, LDA1_B, W1u, LDW_B, acc);
            #pragma unroll
            for (int mf = 0; mf < 4; mf++) {
                int rlo = mf * 16 + erow, rhi = rlo + 8;
                char* dlo = smem + a0b + rlo * LDA0_B;
                char* dhi = smem + a0b + rhi * LDA0_B;
                float alo = 0.f, ahi = 0.f;
                #pragma unroll
                for (int nf = 0; nf < 4; nf++) {
                    int col = cb32 + nf * 8 + ecol;
                    float2 bv = __ldg(reinterpret_cast<const float2*>(b1 + col));
                    float2 wv = *reinterpret_cast<const float2*>(Was + col);
                    float v0 = fmaxf(acc[mf][nf][0] + bv.x, 0.f);
                    float v1 = fmaxf(acc[mf][nf][1] + bv.y, 0.f);
                    float v2 = fmaxf(acc[mf][nf][2] + bv.x, 0.f);
                    float v3 = fmaxf(acc[mf][nf][3] + bv.y, 0.f);
                    alo = fmaf(v0, wv.x, alo); alo = fmaf(v1, wv.y, alo);
                    ahi = fmaf(v2, wv.x, ahi); ahi = fmaf(v3, wv.y, ahi);
                    __half2 h01 = __floats2half2_rn(v0, v1);
                    __half2 h23 = __floats2half2_rn(v2, v3);
                    *reinterpret_cast<uint32_t*>(dlo + col * 2) = *reinterpret_cast<uint32_t*>(&h01);
                    *reinterpret_cast<uint32_t*>(dhi + col * 2) = *reinterpret_cast<uint32_t*>(&h23);
                }
                alo += __shfl_xor_sync(0xffffffffu, alo, 1);
                alo += __shfl_xor_sync(0xffffffffu, alo, 2);
                ahi += __shfl_xor_sync(0xffffffffu, ahi, 1);
                ahi += __shfl_xor_sync(0xffffffffu, ahi, 2);
                if ((lane & 3) == 0) {
                    part[rlo * 16 + hw * 4 + 3] = alo;
                    part[rhi * 16 + hw * 4 + 3] = ahi;
                }
            }
        }
        HBAR(barid);

        // ===== Wc1: hc = relu([h1|denc] @ Wc1 + bc1); rgb partials =====
        {
            float acc[4][2][4];
            #pragma unroll
            for (int mf = 0; mf < 4; mf++)
                #pragma unroll
                for (int i = 0; i < 2; i++)
                    #pragma unroll
                    for (int j = 0; j < 4; j++) acc[mf][i][j] = 0.f;
            mma64<10, 1>(A0u, LDA0_B, Wcu, LDWC_B, acc);
            #pragma unroll
            for (int mf = 0; mf < 4; mf++) {
                int rlo = mf * 16 + erow, rhi = rlo + 8;
                float plo[3] = {0.f, 0.f, 0.f}, phi[3] = {0.f, 0.f, 0.f};
                #pragma unroll
                for (int nf = 0; nf < 2; nf++) {
                    int col = cb16 + nf * 8 + ecol;
                    float2 bcv = *reinterpret_cast<const float2*>(bc1s + col);
                    float v0 = fmaxf(acc[mf][nf][0] + bcv.x, 0.f);
                    float v1 = fmaxf(acc[mf][nf][1] + bcv.y, 0.f);
                    float v2 = fmaxf(acc[mf][nf][2] + bcv.x, 0.f);
                    float v3 = fmaxf(acc[mf][nf][3] + bcv.y, 0.f);
                    #pragma unroll
                    for (int j = 0; j < 3; j++) {
                        float2 w = *reinterpret_cast<const float2*>(Wc2t + j * 64 + col);
                        plo[j] = fmaf(v0, w.x, plo[j]); plo[j] = fmaf(v1, w.y, plo[j]);
                        phi[j] = fmaf(v2, w.x, phi[j]); phi[j] = fmaf(v3, w.y, phi[j]);
                    }
                }
                #pragma unroll
                for (int j = 0; j < 3; j++) {
                    plo[j] += __shfl_xor_sync(0xffffffffu, plo[j], 1);
                    plo[j] += __shfl_xor_sync(0xffffffffu, plo[j], 2);
                    phi[j] += __shfl_xor_sync(0xffffffffu, phi[j], 1);
                    phi[j] += __shfl_xor_sync(0xffffffffu, phi[j], 2);
                }
                if ((lane & 3) == 0) {
                    #pragma unroll
                    for (int j = 0; j < 3; j++) {
                        part[rlo * 16 + hw * 4 + j] = plo[j];
                        part[rhi * 16 + hw * 4 + j] = phi[j];
                    }
                }
            }
        }
        HBAR(barid);

        // ===== combine + scatter (64 threads per half) =====
        if (ht < 64) {
            int gi2 = (tile << 6) + ht;
            if (gi2 < cnt) {
                const float* pp = part + ht * 16;
                float r0 = bc20 + pp[0] + pp[4] + pp[8]  + pp[12];
                float r1 = bc21 + pp[1] + pp[5] + pp[9]  + pp[13];
                float r2 = bc22 + pp[2] + pp[6] + pp[10] + pp[14];
                float aa = ba0  + pp[3] + pp[7] + pp[11] + pp[15];
                float4 outv;
                outv.x = 1.0f / (1.0f + __expf(-r0));
                outv.y = 1.0f / (1.0f + __expf(-r1));
                outv.z = 1.0f / (1.0f + __expf(-r2));
                outv.w = 1.0f / (1.0f + __expf(-aa));
                *reinterpret_cast<float4*>(&g_rgba[g_sidx[gi2] * 4]) = outv;
            }
        }
        HBAR(barid);
    }
}

// ---------------- kernel 5: composite, one warp per ray ----------------
// lane = plane. Sort via warp-bitonic on 37-bit key (ordered_t<<5 | plane),
// transmittance via shfl_up prefix product, outputs via warp reductions.
__global__ void __launch_bounds__(256) k_composite(float* __restrict__ out)
{
    int gw   = (blockIdx.x * blockDim.x + threadIdx.x) >> 5;   // ray
    int lane = threadIdx.x & 31;                                // plane
    if (gw >= N_RAYS) return;
    const int n = gw;

    float t = g_t[lane * N_RAYS + n];
    uint32_t u = __float_as_uint(t);
    u = (u & 0x80000000u) ? ~u : (u | 0x80000000u);            // order-preserving map
    unsigned long long key = ((unsigned long long)u << 5) | (unsigned)lane;

    // bitonic sort across lanes (ascending by t, stable tie-break by plane)
    #pragma unroll
    for (int k = 2; k <= 32; k <<= 1) {
        #pragma unroll
        for (int j = k >> 1; j > 0; j >>= 1) {
            unsigned long long partner = __shfl_xor_sync(0xffffffffu, key, j);
            bool up = ((lane & k) == 0);
            bool takeMin = (((lane & j) == 0) == up);
            bool pLess = partner < key;
            key = (takeMin == pLess) ? partner : key;
        }
    }

    int   sp = (int)(key & 31u);                                // source plane at this rank
    float ts = g_t[sp * N_RAYS + n];
    float4 rg = *reinterpret_cast<const float4*>(&g_rgba[(sp * N_RAYS + n) * 4]);
    float a = rg.w;

    // exclusive prefix product of (1 - a) across lanes
    float om = 1.0f - a;
    float scan = om;
    #pragma unroll
    for (int d = 1; d < 32; d <<= 1) {
        float v = __shfl_up_sync(0xffffffffu, scan, d);
        if (lane >= d) scan *= v;
    }
    float trans = __shfl_up_sync(0xffffffffu, scan, 1);
    if (lane == 0) trans = 1.0f;

    float w  = a * trans;
    float dp = ts * w;
    float c0 = rg.x * w, c1 = rg.y * w, c2 = rg.z * w;

    #pragma unroll
    for (int d = 16; d > 0; d >>= 1) {
        w  += __shfl_xor_sync(0xffffffffu, w, d);
        dp += __shfl_xor_sync(0xffffffffu, dp, d);
        c0 += __shfl_xor_sync(0xffffffffu, c0, d);
        c1 += __shfl_xor_sync(0xffffffffu, c1, d);
        c2 += __shfl_xor_sync(0xffffffffu, c2, d);
    }

    if (lane == 0) {
        float bg = 1.0f - w;
        float4 o;
        o.x = c0 + bg;
        o.y = c1 + bg;
        o.z = c2 + bg;
        o.w = dp;
        *reinterpret_cast<float4*>(&out[n * 4]) = o;
    }
}

// ---------------- launch ----------------
extern "C" void kernel_launch(void* const* d_in, const int* in_sizes, int n_in,
                              void* d_out, int out_size)
{
    const float* ndc    = (const float*)d_in[0];
    const float* campos = (const float*)d_in[1];
    const float* camR   = (const float*)d_in[2];
    const float* basis  = (const float*)d_in[3];
    const float* center = (const float*)d_in[4];
    const float* wh     = (const float*)d_in[5];
    const float* W0     = (const float*)d_in[6];
    const float* b0     = (const float*)d_in[7];
    const float* W1     = (const float*)d_in[8];
    const float* b1     = (const float*)d_in[9];
    const float* Wa     = (const float*)d_in[10];
    const float* ba     = (const float*)d_in[11];
    const float* Wc1    = (const float*)d_in[12];
    const float* bc1    = (const float*)d_in[13];
    const float* Wc2    = (const float*)d_in[14];
    const float* bc2    = (const float*)d_in[15];
    float* out = (float*)d_out;

    static int smem_set = 0;
    if (!smem_set) {
        cudaFuncSetAttribute(k_mlp, cudaFuncAttributeMaxDynamicSharedMemorySize, SMEM_BYTES);
        smem_set = 1;
    }

    k_reset<<<1, 32>>>();
    k_geom<<<NSAMP / 256, 256>>>(ndc, campos, camR, basis, center, wh);
    k_mlp<<<PERSIST_BLOCKS, THREADS, SMEM_BYTES>>>(W0, b0, W1, b1, Wa, ba, Wc1, bc1, Wc2, bc2);
    k_composite<<<(N_RAYS * 32) / 256, 256>>>(out);
}